// round 1
// baseline (speedup 1.0000x reference)
#include <cuda_runtime.h>
#include <math_constants.h>

#define N      4096
#define IT     30
#define NB4    (N / 4)          // float4 per row = 1024
#define CCHUNKS 32
#define ROWS_PER_CHUNK (N / CCHUNKS)   // 128

// Scratch (allocation-free rule: __device__ globals)
static __device__ float  g_B0[(size_t)N * N];    // A0 * log2(e)/TAU  (64 MB)
static __device__ float  g_r[N];
static __device__ float  g_c[N];
static __device__ float2 g_part[CCHUNKS * N];    // column-pass partials (m, s)

// ---------------------------------------------------------------------------
// Setup: B0 = (mean + std*eps) * (log2(e)/TAU); zero c.
// ---------------------------------------------------------------------------
__global__ void setup_kernel(const float* __restrict__ eps,
                             const float* __restrict__ mean,
                             const float* __restrict__ stdv) {
    const float SCALE = 0.72134752044448170368f;  // log2(e) / 2.0
    int idx = blockIdx.x * blockDim.x + threadIdx.x;  // float4 index
    const float4 e = ((const float4*)eps)[idx];
    const float4 m = ((const float4*)mean)[idx];
    const float4 s = ((const float4*)stdv)[idx];
    float4 o;
    o.x = (m.x + s.x * e.x) * SCALE;
    o.y = (m.y + s.y * e.y) * SCALE;
    o.z = (m.z + s.z * e.z) * SCALE;
    o.w = (m.w + s.w * e.w) * SCALE;
    ((float4*)g_B0)[idx] = o;
    if (idx < N / 4) ((float4*)g_c)[idx] = make_float4(0.f, 0.f, 0.f, 0.f);
}

// Branchless chunked online log2-sum-exp2 accumulate of 4 values.
__device__ __forceinline__ void lse4(float& m, float& s,
                                     float x0, float x1, float x2, float x3) {
    float cm = fmaxf(fmaxf(x0, x1), fmaxf(x2, x3));
    float nm = fmaxf(m, cm);
    s = s * exp2f(m - nm)
        + (exp2f(x0 - nm) + exp2f(x1 - nm))
        + (exp2f(x2 - nm) + exp2f(x3 - nm));
    m = nm;
}

// ---------------------------------------------------------------------------
// Row pass: r(i) = log2 sum_j 2^(B0(i,j) - c(j)).  One block per row.
// ---------------------------------------------------------------------------
__global__ void row_lse_kernel() {
    const int row = blockIdx.x;
    const int t   = threadIdx.x;             // 256 threads
    const float4* __restrict__ b4 = (const float4*)(g_B0 + (size_t)row * N);
    const float4* __restrict__ c4 = (const float4*)g_c;

    float m = -CUDART_INF_F, s = 0.f;
    #pragma unroll
    for (int k = 0; k < 4; k++) {
        float4 b = b4[k * 256 + t];
        float4 c = c4[k * 256 + t];
        lse4(m, s, b.x - c.x, b.y - c.y, b.z - c.z, b.w - c.w);
    }

    // warp reduce (combine (m,s) pairs)
    #pragma unroll
    for (int off = 16; off > 0; off >>= 1) {
        float om = __shfl_xor_sync(0xffffffffu, m, off);
        float os = __shfl_xor_sync(0xffffffffu, s, off);
        float nm = fmaxf(m, om);
        s = s * exp2f(m - nm) + os * exp2f(om - nm);
        m = nm;
    }

    __shared__ float sm[8], ss[8];
    if ((t & 31) == 0) { sm[t >> 5] = m; ss[t >> 5] = s; }
    __syncthreads();
    if (t == 0) {
        float fm = sm[0], fs = ss[0];
        #pragma unroll
        for (int w = 1; w < 8; w++) {
            float nm = fmaxf(fm, sm[w]);
            fs = fs * exp2f(fm - nm) + ss[w] * exp2f(sm[w] - nm);
            fm = nm;
        }
        g_r[row] = fm + log2f(fs);
    }
}

// ---------------------------------------------------------------------------
// Column pass, stage 1: per-(128-row chunk) partial LSE for each column.
// grid = (N/256, CCHUNKS), block = 256; thread owns one column.
// ---------------------------------------------------------------------------
__global__ void col_part_kernel() {
    const int j  = blockIdx.x * 256 + threadIdx.x;
    const int i0 = blockIdx.y * ROWS_PER_CHUNK;
    const float* __restrict__ base = g_B0 + (size_t)i0 * N + j;
    const float* __restrict__ rp   = g_r + i0;

    float m = -CUDART_INF_F, s = 0.f;
    #pragma unroll 4
    for (int i = 0; i < ROWS_PER_CHUNK; i += 4) {
        float x0 = base[(i + 0) * N] - rp[i + 0];
        float x1 = base[(i + 1) * N] - rp[i + 1];
        float x2 = base[(i + 2) * N] - rp[i + 2];
        float x3 = base[(i + 3) * N] - rp[i + 3];
        lse4(m, s, x0, x1, x2, x3);
    }
    g_part[blockIdx.y * N + j] = make_float2(m, s);
}

// Column pass, stage 2: combine CCHUNKS partials -> c(j).
__global__ void col_combine_kernel() {
    const int j = blockIdx.x * 256 + threadIdx.x;
    float m = -CUDART_INF_F, s = 0.f;
    #pragma unroll
    for (int k = 0; k < CCHUNKS; k++) {
        float2 p = g_part[k * N + j];
        float nm = fmaxf(m, p.x);
        s = s * exp2f(m - nm) + p.y * exp2f(p.x - nm);
        m = nm;
    }
    g_c[j] = m + log2f(s);
}

// ---------------------------------------------------------------------------
// Finalize: out = 2^(B0 - r(i) - c(j))
// ---------------------------------------------------------------------------
__global__ void final_kernel(float* __restrict__ out) {
    int idx = blockIdx.x * blockDim.x + threadIdx.x;  // float4 index
    int row = idx >> 10;        // NB4 = 1024 float4 per row
    int cj  = idx & (NB4 - 1);
    float4 b  = ((const float4*)g_B0)[idx];
    float4 cc = ((const float4*)g_c)[cj];
    float  rv = g_r[row];
    float4 o;
    o.x = exp2f(b.x - rv - cc.x);
    o.y = exp2f(b.y - rv - cc.y);
    o.z = exp2f(b.z - rv - cc.z);
    o.w = exp2f(b.w - rv - cc.w);
    ((float4*)out)[idx] = o;
}

// ---------------------------------------------------------------------------
extern "C" void kernel_launch(void* const* d_in, const int* in_sizes, int n_in,
                              void* d_out, int out_size) {
    const float* eps  = (const float*)d_in[0];
    const float* mean = (const float*)d_in[1];
    const float* stdv = (const float*)d_in[2];
    float* out = (float*)d_out;

    const int n4 = N * N / 4;                 // float4 elements
    setup_kernel<<<n4 / 256, 256>>>(eps, mean, stdv);

    for (int it = 0; it < IT; it++) {
        row_lse_kernel<<<N, 256>>>();
        col_part_kernel<<<dim3(N / 256, CCHUNKS), 256>>>();
        col_combine_kernel<<<N / 256, 256>>>();
    }

    final_kernel<<<n4 / 256, 256>>>(out);
}